// round 16
// baseline (speedup 1.0000x reference)
#include <cuda_runtime.h>
#include <cuda_bf16.h>
#include <cuda_fp16.h>
#include <cstdint>

#define LL   512
#define DD   64
#define OD   1024
#define QKSCALE 0.125f
#define WSCALE 64.0f
#define WINV   0.015625f

// Projected Q/K in [head][p][d]; V stored TRANSPOSED: [head][d][p]
__device__ float g_Q[64 * LL * DD];
__device__ float g_K[64 * LL * DD];
__device__ float g_V[64 * LL * DD];

// ---------------------------------------------------------------------------
__device__ __forceinline__ uint32_t smem_u32(const void* p) {
    uint32_t a;
    asm("{ .reg .u64 t; cvta.to.shared.u64 t, %1; cvt.u32.u64 %0, t; }"
        : "=r"(a) : "l"(p));
    return a;
}

__device__ __forceinline__ void ldm4(uint32_t* r, uint32_t addr) {
    asm volatile("ldmatrix.sync.aligned.m8n8.x4.shared.b16 {%0,%1,%2,%3}, [%4];"
                 : "=r"(r[0]), "=r"(r[1]), "=r"(r[2]), "=r"(r[3]) : "r"(addr));
}

__device__ __forceinline__ void mma_bf16(float* c, const uint32_t* a,
                                         const uint32_t* b) {
    asm volatile(
        "mma.sync.aligned.m16n8k16.row.col.f32.bf16.bf16.f32 "
        "{%0,%1,%2,%3}, {%4,%5,%6,%7}, {%8,%9}, {%0,%1,%2,%3};"
        : "+f"(c[0]), "+f"(c[1]), "+f"(c[2]), "+f"(c[3])
        : "r"(a[0]), "r"(a[1]), "r"(a[2]), "r"(a[3]), "r"(b[0]), "r"(b[1]));
}

__device__ __forceinline__ void mma_f16(float* c, const uint32_t* a,
                                        const uint32_t* b) {
    asm volatile(
        "mma.sync.aligned.m16n8k16.row.col.f32.f16.f16.f32 "
        "{%0,%1,%2,%3}, {%4,%5,%6,%7}, {%8,%9}, {%0,%1,%2,%3};"
        : "+f"(c[0]), "+f"(c[1]), "+f"(c[2]), "+f"(c[3])
        : "r"(a[0]), "r"(a[1]), "r"(a[2]), "r"(a[3]), "r"(b[0]), "r"(b[1]));
}

// PRMT truncation split: hi = top16(f), lo = bf16(f - hi)
__device__ __forceinline__ void split2(float f0, float f1,
                                       uint32_t& hi, uint32_t& lo) {
    uint32_t u0 = __float_as_uint(f0), u1 = __float_as_uint(f1);
    hi = __byte_perm(u0, u1, 0x7632);
    float l0 = f0 - __uint_as_float(u0 & 0xFFFF0000u);
    float l1 = f1 - __uint_as_float(u1 & 0xFFFF0000u);
    lo = __byte_perm(__float_as_uint(l0), __float_as_uint(l1), 0x7632);
}

__device__ __forceinline__ void split_store_x(char* smb, uint32_t hi_off,
                                              uint32_t lo_off, float4 v) {
    uint2 hv, lv;
    split2(v.x, v.y, hv.x, lv.x);
    split2(v.z, v.w, hv.y, lv.y);
    *(uint2*)(smb + hi_off) = hv;
    *(uint2*)(smb + lo_off) = lv;
}

__device__ __forceinline__ uint32_t h2bits(float a, float b) {
    __half2 h = __float22half2_rn(make_float2(a, b));
    return *reinterpret_cast<uint32_t*>(&h);
}

// fp16 hi/lo split of a float pair
__device__ __forceinline__ void split2_h(float f0, float f1,
                                         uint32_t& hi, uint32_t& lo) {
    __half2 h = __float22half2_rn(make_float2(f0, f1));
    float2 f = __half22float2(h);
    __half2 l = __float22half2_rn(make_float2(f0 - f.x, f1 - f.y));
    hi = *reinterpret_cast<uint32_t*>(&h);
    lo = *reinterpret_cast<uint32_t*>(&l);
}

// single-fp16 store (for proj A operand)
__device__ __forceinline__ void store_x_h(char* smb, uint32_t off, float4 v) {
    uint2 hv;
    hv.x = h2bits(v.x, v.y);
    hv.y = h2bits(v.z, v.w);
    *(uint2*)(smb + off) = hv;
}

// scale W row by 64 and split-store fp16 hi/lo planes
__device__ __forceinline__ void split_store_w(char* smb, uint32_t hi_off,
                                              uint32_t lo_off, float4 v) {
    uint2 hv, lv;
    split2_h(v.x * WSCALE, v.y * WSCALE, hv.x, lv.x);
    split2_h(v.z * WSCALE, v.w * WSCALE, hv.y, lv.y);
    *(uint2*)(smb + hi_off) = hv;
    *(uint2*)(smb + lo_off) = lv;
}

// fp16 hi/lo split store (for attention V)
__device__ __forceinline__ void split_store_v(char* smb, uint32_t hi_off,
                                              uint32_t lo_off, float4 v) {
    uint2 hv, lv;
    split2_h(v.x, v.y, hv.x, lv.x);
    split2_h(v.z, v.w, hv.y, lv.y);
    *(uint2*)(smb + hi_off) = hv;
    *(uint2*)(smb + lo_off) = lv;
}

// ---------------------------------------------------------------------------
// Projection (R14-proven: wsplit folded in, 2-stage pipeline).
// ---------------------------------------------------------------------------
#define KCH   64
#define NIT   (OD / KCH)
#define ROWP  144
#define A_H   0
#define B_HI  18432
#define B_LO  27648
#define STG   36864
#define PROJ_SMEM (2 * STG)

__global__ __launch_bounds__(256, 2) void proj_tc(
    const float* __restrict__ Qs, const float* __restrict__ Ks,
    const float* __restrict__ Vs,
    const float* __restrict__ WQ, const float* __restrict__ WK,
    const float* __restrict__ WV,
    const float* __restrict__ bQ, const float* __restrict__ bK,
    const float* __restrict__ bV,
    float* __restrict__ YQ, float* __restrict__ YK, float* __restrict__ YV)
{
    extern __shared__ char sm[];
    const int t    = threadIdx.x;
    const int wid  = t >> 5;
    const int lane = t & 31;
    const int wr   = wid & 3;
    const int wc   = wid >> 2;

    const float *X, *W, *bias;
    float* Y;
    if (blockIdx.y == 0)      { X = Qs; W = WQ; bias = bQ; Y = YQ; }
    else if (blockIdx.y == 1) { X = Ks; W = WK; bias = bK; Y = YK; }
    else                      { X = Vs; W = WV; bias = bV; Y = YV; }
    const int mat = blockIdx.y;

    const int row0 = blockIdx.x * 128;
    const uint32_t sb = smem_u32(sm);

    const uint32_t a_row_off = (uint32_t)(wr * 32 + (lane & 15)) * ROWP
                             + ((lane >> 4) & 1) * 16;
    const uint32_t b_row_off = (uint32_t)((lane & 7) + ((lane & 16) >> 1)) * ROWP
                             + ((lane & 8) << 1);

    const int rA = t >> 4;
    const int cA = t & 15;

    const float* xbase = X + (size_t)(row0 + rA) * OD + cA * 4;
    const float* wbase = W + (size_t)rA * OD + cA * 4;

    float acc[2][4][4];
#pragma unroll
    for (int mt = 0; mt < 2; mt++)
#pragma unroll
        for (int nt = 0; nt < 4; nt++)
#pragma unroll
            for (int j = 0; j < 4; j++) acc[mt][nt][j] = 0.f;

    float4 xr[8], wr4[4];
#pragma unroll
    for (int p = 0; p < 8; p++)
        xr[p] = *(const float4*)(xbase + (size_t)(p * 16) * OD);
#pragma unroll
    for (int p = 0; p < 4; p++)
        wr4[p] = *(const float4*)(wbase + (size_t)(p * 16) * OD);
#pragma unroll
    for (int p = 0; p < 8; p++) {
        uint32_t off = (uint32_t)(rA + p * 16) * ROWP + cA * 8;
        store_x_h(sm, A_H + off, xr[p]);
    }
#pragma unroll
    for (int p = 0; p < 4; p++) {
        uint32_t off = (uint32_t)(rA + p * 16) * ROWP + cA * 8;
        split_store_w(sm, B_HI + off, B_LO + off, wr4[p]);
    }
#pragma unroll
    for (int p = 0; p < 8; p++)
        xr[p] = *(const float4*)(xbase + (size_t)(p * 16) * OD + KCH);
#pragma unroll
    for (int p = 0; p < 4; p++)
        wr4[p] = *(const float4*)(wbase + (size_t)(p * 16) * OD + KCH);
    __syncthreads();

    for (int it = 0; it < NIT; ++it) {
        const uint32_t cur = (uint32_t)(it & 1) * STG;
        const uint32_t nxt = cur ^ STG;

        if (it + 1 < NIT) {
#pragma unroll
            for (int p = 0; p < 8; p++) {
                uint32_t off = (uint32_t)(rA + p * 16) * ROWP + cA * 8;
                store_x_h(sm, nxt + A_H + off, xr[p]);
            }
#pragma unroll
            for (int p = 0; p < 4; p++) {
                uint32_t off = (uint32_t)(rA + p * 16) * ROWP + cA * 8;
                split_store_w(sm, nxt + B_HI + off, nxt + B_LO + off, wr4[p]);
            }
        }
        if (it + 2 < NIT) {
            const int k2 = (it + 2) * KCH;
#pragma unroll
            for (int p = 0; p < 8; p++)
                xr[p] = *(const float4*)(xbase + (size_t)(p * 16) * OD + k2);
#pragma unroll
            for (int p = 0; p < 4; p++)
                wr4[p] = *(const float4*)(wbase + (size_t)(p * 16) * OD + k2);
        }

#pragma unroll
        for (int ks = 0; ks < 4; ks++) {
            uint32_t ah[2][4];
#pragma unroll
            for (int mt = 0; mt < 2; mt++) {
                uint32_t ao = cur + a_row_off + (uint32_t)mt * 16 * ROWP
                            + ks * 32;
                ldm4(ah[mt], sb + A_H + ao);
            }
#pragma unroll
            for (int nb = 0; nb < 2; nb++) {
                uint32_t bo = cur + b_row_off
                            + (uint32_t)(wc * 32 + nb * 16) * ROWP + ks * 32;
                uint32_t bh[4], bl[4];
                ldm4(bh, sb + B_HI + bo);
                ldm4(bl, sb + B_LO + bo);
#pragma unroll
                for (int mt = 0; mt < 2; mt++) {
#pragma unroll
                    for (int h = 0; h < 2; h++) {
                        float* c = acc[mt][nb * 2 + h];
                        mma_f16(c, ah[mt], bh + h * 2);
                        mma_f16(c, ah[mt], bl + h * 2);
                    }
                }
            }
        }
        __syncthreads();
    }

    if (mat != 2) {
#pragma unroll
        for (int nt = 0; nt < 4; nt++) {
            int n0 = wc * 32 + nt * 8 + (lane & 3) * 2;
            float b0 = bias[n0], b1 = bias[n0 + 1];
#pragma unroll
            for (int mt = 0; mt < 2; mt++) {
#pragma unroll
                for (int ro = 0; ro < 2; ro++) {
                    int grow = row0 + wr * 32 + mt * 16 + (lane >> 2) + ro * 8;
                    int b = grow >> 9, l = grow & 511;
                    int x = b >> 4, mm = l & 15, pp = ((b & 15) << 5) | (l >> 4);
                    int hh = (x << 4) | mm;
                    float2 o = make_float2(
                        acc[mt][nt][ro * 2 + 0] * WINV + b0,
                        acc[mt][nt][ro * 2 + 1] * WINV + b1);
                    *(float2*)(Y + ((size_t)hh * LL + pp) * DD + n0) = o;
                }
            }
        }
    } else {
        float* smf = (float*)sm;
#pragma unroll
        for (int nt = 0; nt < 4; nt++) {
            int n0 = wc * 32 + nt * 8 + (lane & 3) * 2;
            float b0 = bias[n0], b1 = bias[n0 + 1];
#pragma unroll
            for (int mt = 0; mt < 2; mt++) {
#pragma unroll
                for (int ro = 0; ro < 2; ro++) {
                    int r = wr * 32 + mt * 16 + (lane >> 2) + ro * 8;
                    smf[r * 65 + n0]     = acc[mt][nt][ro * 2 + 0] * WINV + b0;
                    smf[r * 65 + n0 + 1] = acc[mt][nt][ro * 2 + 1] * WINV + b1;
                }
            }
        }
        __syncthreads();

        const int bb  = row0 >> 9;
        const int xb  = bb >> 4;
        const int ppb = ((bb & 15) << 5) + ((row0 & 511) >> 4);
#pragma unroll
        for (int s = 0; s < 4; s++) {
            int idx = t + 256 * s;
            int hl  = idx & 15;
            int d   = idx >> 4;
            int hh  = (xb << 4) | hl;
            float v0 = smf[(hl + 16 * 0) * 65 + d];
            float v1 = smf[(hl + 16 * 1) * 65 + d];
            float v2 = smf[(hl + 16 * 2) * 65 + d];
            float v3 = smf[(hl + 16 * 3) * 65 + d];
            float v4 = smf[(hl + 16 * 4) * 65 + d];
            float v5 = smf[(hl + 16 * 5) * 65 + d];
            float v6 = smf[(hl + 16 * 6) * 65 + d];
            float v7 = smf[(hl + 16 * 7) * 65 + d];
            float* dst = Y + ((size_t)hh * DD + d) * LL + ppb;
            *(float4*)(dst)     = make_float4(v0, v1, v2, v3);
            *(float4*)(dst + 4) = make_float4(v4, v5, v6, v7);
        }
    }
}

// ---------------------------------------------------------------------------
// Tensor-core flash attention — 128-thread CTAs, reg-capped for 4 CTAs/SM.
// ---------------------------------------------------------------------------
#define AQH 0
#define AQL 9216
#define AKH 18432
#define AKL 27648
#define AVH 36864
#define AVL 46080
#define ATTN_SMEM 55296

__global__ __launch_bounds__(128, 4) void attn_tc(
    const int* __restrict__ Q_len, const int* __restrict__ V_len,
    float* __restrict__ out)
{
    const int hh = blockIdx.x;
    const int q0 = (7 - blockIdx.y) << 6;   // heavy tiles first
    const int x  = hh >> 4;
    const int mm = hh & 15;
    const int qlen = Q_len[x];
    const int vlen = V_len[x];
    const int t    = threadIdx.x;
    const int wid  = t >> 5;                // 0..3
    const int lane = t & 31;

    float* outb = out + (size_t)x * LL * OD + (size_t)mm * DD;

    if (q0 >= qlen) {
#pragma unroll
        for (int s = 0; s < 8; s++) {
            int v  = t + 128 * s;           // 0..1023
            int r  = v >> 4;                // 0..63
            int dd = (v & 15) << 2;
            *(float4*)(outb + (size_t)(q0 + r) * OD + dd) =
                make_float4(0.f, 0.f, 0.f, 0.f);
        }
        return;
    }

    extern __shared__ char sm[];
    const uint32_t sb = smem_u32(sm);

    // stage Q (64 rows x 64 d) as bf16 hi/lo
    const float* Qg = g_Q + ((size_t)hh * LL + q0) * DD;
#pragma unroll
    for (int s = 0; s < 8; s++) {
        int v  = t + 128 * s;
        int r  = v >> 4;
        int dd = (v & 15) << 2;
        float4 qv = *(const float4*)(Qg + r * DD + dd);
        uint32_t off = (uint32_t)r * ROWP + dd * 2;
        split_store_x(sm, AQH + off, AQL + off, qv);
    }

    const uint32_t aoff = (uint32_t)(wid * 16 + (lane & 15)) * ROWP
                        + ((lane >> 4) & 1) * 16;
    const uint32_t boff = (uint32_t)((lane & 7) + ((lane & 16) >> 1)) * ROWP
                        + ((lane & 8) << 1);

    const int rq0 = q0 + wid * 16 + (lane >> 2);
    const int rq1 = rq0 + 8;

    float o_[8][4];
#pragma unroll
    for (int nt = 0; nt < 8; nt++)
#pragma unroll
        for (int j = 0; j < 4; j++) o_[nt][j] = 0.f;
    float m0 = -1e30f, m1 = -1e30f, l0 = 0.f, l1 = 0.f;

    const int kmaxi = min(q0 + 63, vlen - 1);
    const int nkt   = kmaxi >> 6;

    for (int kt = 0; kt <= nkt; kt++) {
        const int k0 = kt << 6;
        __syncthreads();
        const float* Kg = g_K + ((size_t)hh * LL + k0) * DD;
#pragma unroll
        for (int s = 0; s < 8; s++) {
            int v  = t + 128 * s;
            int r  = v >> 4;
            int dd = (v & 15) << 2;
            uint32_t off = (uint32_t)r * ROWP + dd * 2;
            float4 kv = *(const float4*)(Kg + r * DD + dd);
            split_store_x(sm, AKH + off, AKL + off, kv);
            float4 vv = *(const float4*)(g_V + ((size_t)hh * DD + r) * LL
                                         + k0 + dd);
            split_store_v(sm, AVH + off, AVL + off, vv);
        }
        __syncthreads();

        // ---- S = Q K^T (bf16 3-term) ----
        float s_[8][4];
#pragma unroll
        for (int nt = 0; nt < 8; nt++)
#pragma unroll
            for (int j = 0; j < 4; j++) s_[nt][j] = 0.f;

#pragma unroll
        for (int ks = 0; ks < 4; ks++) {
            uint32_t qh[4], ql[4];
            ldm4(qh, sb + AQH + aoff + ks * 32);
            ldm4(ql, sb + AQL + aoff + ks * 32);
#pragma unroll
            for (int nb = 0; nb < 4; nb++) {
                uint32_t base = sb + AKH + boff + (uint32_t)nb * 16 * ROWP
                              + ks * 32;
                uint32_t kh[4], kl[4];
                ldm4(kh, base);
                ldm4(kl, base + 9216);
#pragma unroll
                for (int h = 0; h < 2; h++) {
                    float* c = s_[nb * 2 + h];
                    mma_bf16(c, qh, kh + h * 2);
                    mma_bf16(c, qh, kl + h * 2);
                    mma_bf16(c, ql, kh + h * 2);
                }
            }
        }

        // ---- mask + scale ----
#pragma unroll
        for (int nt = 0; nt < 8; nt++) {
#pragma unroll
            for (int c = 0; c < 2; c++) {
                int k = k0 + nt * 8 + (lane & 3) * 2 + c;
                bool kv_ok = (k < vlen);
                s_[nt][c]     = (kv_ok && k <= rq0) ? s_[nt][c] * QKSCALE
                                                    : -1e30f;
                s_[nt][2 + c] = (kv_ok && k <= rq1) ? s_[nt][2 + c] * QKSCALE
                                                    : -1e30f;
            }
        }

        // ---- online softmax ----
        float tm0 = -1e30f, tm1 = -1e30f;
#pragma unroll
        for (int nt = 0; nt < 8; nt++) {
            tm0 = fmaxf(tm0, fmaxf(s_[nt][0], s_[nt][1]));
            tm1 = fmaxf(tm1, fmaxf(s_[nt][2], s_[nt][3]));
        }
        tm0 = fmaxf(tm0, __shfl_xor_sync(0xffffffffu, tm0, 1));
        tm0 = fmaxf(tm0, __shfl_xor_sync(0xffffffffu, tm0, 2));
        tm1 = fmaxf(tm1, __shfl_xor_sync(0xffffffffu, tm1, 1));
        tm1 = fmaxf(tm1, __shfl_xor_sync(0xffffffffu, tm1, 2));

        float mn0 = fmaxf(m0, tm0), mn1 = fmaxf(m1, tm1);
        float a0 = __expf(m0 - mn0), a1 = __expf(m1 - mn1);
        float sum0 = 0.f, sum1 = 0.f;
#pragma unroll
        for (int nt = 0; nt < 8; nt++) {
            float p0 = __expf(s_[nt][0] - mn0);
            float p1 = __expf(s_[nt][1] - mn0);
            float p2 = __expf(s_[nt][2] - mn1);
            float p3 = __expf(s_[nt][3] - mn1);
            s_[nt][0] = p0; s_[nt][1] = p1; s_[nt][2] = p2; s_[nt][3] = p3;
            sum0 += p0 + p1;
            sum1 += p2 + p3;
        }
        sum0 += __shfl_xor_sync(0xffffffffu, sum0, 1);
        sum0 += __shfl_xor_sync(0xffffffffu, sum0, 2);
        sum1 += __shfl_xor_sync(0xffffffffu, sum1, 1);
        sum1 += __shfl_xor_sync(0xffffffffu, sum1, 2);
        m0 = mn0; m1 = mn1;
        l0 = l0 * a0 + sum0;
        l1 = l1 * a1 + sum1;
#pragma unroll
        for (int nt = 0; nt < 8; nt++) {
            o_[nt][0] *= a0; o_[nt][1] *= a0;
            o_[nt][2] *= a1; o_[nt][3] *= a1;
        }

        // ---- O += P V  (P single fp16, V fp16 hi/lo: 2 MMAs) ----
#pragma unroll
        for (int j = 0; j < 4; j++) {
            uint32_t ph[4];
            ph[0] = h2bits(s_[2 * j][0],     s_[2 * j][1]);
            ph[1] = h2bits(s_[2 * j][2],     s_[2 * j][3]);
            ph[2] = h2bits(s_[2 * j + 1][0], s_[2 * j + 1][1]);
            ph[3] = h2bits(s_[2 * j + 1][2], s_[2 * j + 1][3]);
#pragma unroll
            for (int nb = 0; nb < 4; nb++) {
                uint32_t base = sb + AVH + boff + (uint32_t)nb * 16 * ROWP
                              + j * 32;
                uint32_t vh[4], vl[4];
                ldm4(vh, base);
                ldm4(vl, base + 9216);
#pragma unroll
                for (int h = 0; h < 2; h++) {
                    float* c = o_[nb * 2 + h];
                    mma_f16(c, ph, vh + h * 2);
                    mma_f16(c, ph, vl + h * 2);
                }
            }
        }
    }

    // ---- epilogue ----
    float inv0 = 1.f / l0, inv1 = 1.f / l1;
    bool ok0 = (rq0 < qlen), ok1 = (rq1 < qlen);
#pragma unroll
    for (int nt = 0; nt < 8; nt++) {
        int d = nt * 8 + (lane & 3) * 2;
        float2 w0, w1;
        w0.x = ok0 ? o_[nt][0] * inv0 : 0.f;
        w0.y = ok0 ? o_[nt][1] * inv0 : 0.f;
        w1.x = ok1 ? o_[nt][2] * inv1 : 0.f;
        w1.y = ok1 ? o_[nt][3] * inv1 : 0.f;
        *(float2*)(outb + (size_t)rq0 * OD + d) = w0;
        *(float2*)(outb + (size_t)rq1 * OD + d) = w1;
    }
}

// ---------------------------------------------------------------------------
extern "C" void kernel_launch(void* const* d_in, const int* in_sizes, int n_in,
                              void* d_out, int out_size)
{
    (void)in_sizes; (void)n_in; (void)out_size;
    const float* Qseq = (const float*)d_in[0];
    const float* Kseq = (const float*)d_in[1];
    const float* Vseq = (const float*)d_in[2];
    const int*   Qlen = (const int*)d_in[3];
    const int*   Vlen = (const int*)d_in[4];
    const float* WQw  = (const float*)d_in[5];
    const float* WQb  = (const float*)d_in[6];
    const float* WKw  = (const float*)d_in[7];
    const float* WKb  = (const float*)d_in[8];
    const float* WVw  = (const float*)d_in[9];
    const float* WVb  = (const float*)d_in[10];
    float* out = (float*)d_out;

    float *pQ = nullptr, *pK = nullptr, *pV = nullptr;
    cudaGetSymbolAddress((void**)&pQ, g_Q);
    cudaGetSymbolAddress((void**)&pK, g_K);
    cudaGetSymbolAddress((void**)&pV, g_V);

    cudaFuncSetAttribute(proj_tc,
                         cudaFuncAttributeMaxDynamicSharedMemorySize, PROJ_SMEM);
    cudaFuncSetAttribute(attn_tc,
                         cudaFuncAttributeMaxDynamicSharedMemorySize, ATTN_SMEM);

    dim3 pg(256, 3);
    proj_tc<<<pg, 256, PROJ_SMEM>>>(Qseq, Kseq, Vseq,
                                    WQw, WKw, WVw,
                                    WQb, WKb, WVb,
                                    pQ, pK, pV);

    dim3 grid(64, 8);
    attn_tc<<<grid, 128, ATTN_SMEM>>>(Qlen, Vlen, out);
}

// round 17
// speedup vs baseline: 1.0453x; 1.0453x over previous
#include <cuda_runtime.h>
#include <cuda_bf16.h>
#include <cuda_fp16.h>
#include <cstdint>

#define LL   512
#define DD   64
#define OD   1024
#define QKSCALE 0.125f
#define WSCALE 64.0f
#define WINV   0.015625f

// Projected Q/K in fp16 [head][p][d]; V fp16 TRANSPOSED [head][d][p]
__device__ __half g_Qh[64 * LL * DD];
__device__ __half g_Kh[64 * LL * DD];
__device__ __half g_Vh[64 * LL * DD];

// ---------------------------------------------------------------------------
__device__ __forceinline__ uint32_t smem_u32(const void* p) {
    uint32_t a;
    asm("{ .reg .u64 t; cvta.to.shared.u64 t, %1; cvt.u32.u64 %0, t; }"
        : "=r"(a) : "l"(p));
    return a;
}

__device__ __forceinline__ void ldm4(uint32_t* r, uint32_t addr) {
    asm volatile("ldmatrix.sync.aligned.m8n8.x4.shared.b16 {%0,%1,%2,%3}, [%4];"
                 : "=r"(r[0]), "=r"(r[1]), "=r"(r[2]), "=r"(r[3]) : "r"(addr));
}

__device__ __forceinline__ void mma_f16(float* c, const uint32_t* a,
                                        const uint32_t* b) {
    asm volatile(
        "mma.sync.aligned.m16n8k16.row.col.f32.f16.f16.f32 "
        "{%0,%1,%2,%3}, {%4,%5,%6,%7}, {%8,%9}, {%0,%1,%2,%3};"
        : "+f"(c[0]), "+f"(c[1]), "+f"(c[2]), "+f"(c[3])
        : "r"(a[0]), "r"(a[1]), "r"(a[2]), "r"(a[3]), "r"(b[0]), "r"(b[1]));
}

__device__ __forceinline__ uint32_t h2bits(float a, float b) {
    __half2 h = __float22half2_rn(make_float2(a, b));
    return *reinterpret_cast<uint32_t*>(&h);
}

// fp16 hi/lo split of a float pair
__device__ __forceinline__ void split2_h(float f0, float f1,
                                         uint32_t& hi, uint32_t& lo) {
    __half2 h = __float22half2_rn(make_float2(f0, f1));
    float2 f = __half22float2(h);
    __half2 l = __float22half2_rn(make_float2(f0 - f.x, f1 - f.y));
    hi = *reinterpret_cast<uint32_t*>(&h);
    lo = *reinterpret_cast<uint32_t*>(&l);
}

// single-fp16 store (for proj A operand)
__device__ __forceinline__ void store_x_h(char* smb, uint32_t off, float4 v) {
    uint2 hv;
    hv.x = h2bits(v.x, v.y);
    hv.y = h2bits(v.z, v.w);
    *(uint2*)(smb + off) = hv;
}

// scale W row by 64 and split-store fp16 hi/lo planes
__device__ __forceinline__ void split_store_w(char* smb, uint32_t hi_off,
                                              uint32_t lo_off, float4 v) {
    uint2 hv, lv;
    split2_h(v.x * WSCALE, v.y * WSCALE, hv.x, lv.x);
    split2_h(v.z * WSCALE, v.w * WSCALE, hv.y, lv.y);
    *(uint2*)(smb + hi_off) = hv;
    *(uint2*)(smb + lo_off) = lv;
}

// ---------------------------------------------------------------------------
// Projection (R14-proven mainloop: wsplit folded in, 2-stage pipeline).
// Epilogue writes SINGLE fp16 outputs (Q/K direct, V transposed via smem).
// ---------------------------------------------------------------------------
#define KCH   64
#define NIT   (OD / KCH)
#define ROWP  144
#define A_H   0
#define B_HI  18432
#define B_LO  27648
#define STG   36864
#define PROJ_SMEM (2 * STG)

__global__ __launch_bounds__(256, 2) void proj_tc(
    const float* __restrict__ Qs, const float* __restrict__ Ks,
    const float* __restrict__ Vs,
    const float* __restrict__ WQ, const float* __restrict__ WK,
    const float* __restrict__ WV,
    const float* __restrict__ bQ, const float* __restrict__ bK,
    const float* __restrict__ bV)
{
    extern __shared__ char sm[];
    const int t    = threadIdx.x;
    const int wid  = t >> 5;
    const int lane = t & 31;
    const int wr   = wid & 3;
    const int wc   = wid >> 2;

    const float *X, *W, *bias;
    if (blockIdx.y == 0)      { X = Qs; W = WQ; bias = bQ; }
    else if (blockIdx.y == 1) { X = Ks; W = WK; bias = bK; }
    else                      { X = Vs; W = WV; bias = bV; }
    const int mat = blockIdx.y;

    const int row0 = blockIdx.x * 128;
    const uint32_t sb = smem_u32(sm);

    const uint32_t a_row_off = (uint32_t)(wr * 32 + (lane & 15)) * ROWP
                             + ((lane >> 4) & 1) * 16;
    const uint32_t b_row_off = (uint32_t)((lane & 7) + ((lane & 16) >> 1)) * ROWP
                             + ((lane & 8) << 1);

    const int rA = t >> 4;
    const int cA = t & 15;

    const float* xbase = X + (size_t)(row0 + rA) * OD + cA * 4;
    const float* wbase = W + (size_t)rA * OD + cA * 4;

    float acc[2][4][4];
#pragma unroll
    for (int mt = 0; mt < 2; mt++)
#pragma unroll
        for (int nt = 0; nt < 4; nt++)
#pragma unroll
            for (int j = 0; j < 4; j++) acc[mt][nt][j] = 0.f;

    float4 xr[8], wr4[4];
#pragma unroll
    for (int p = 0; p < 8; p++)
        xr[p] = *(const float4*)(xbase + (size_t)(p * 16) * OD);
#pragma unroll
    for (int p = 0; p < 4; p++)
        wr4[p] = *(const float4*)(wbase + (size_t)(p * 16) * OD);
#pragma unroll
    for (int p = 0; p < 8; p++) {
        uint32_t off = (uint32_t)(rA + p * 16) * ROWP + cA * 8;
        store_x_h(sm, A_H + off, xr[p]);
    }
#pragma unroll
    for (int p = 0; p < 4; p++) {
        uint32_t off = (uint32_t)(rA + p * 16) * ROWP + cA * 8;
        split_store_w(sm, B_HI + off, B_LO + off, wr4[p]);
    }
#pragma unroll
    for (int p = 0; p < 8; p++)
        xr[p] = *(const float4*)(xbase + (size_t)(p * 16) * OD + KCH);
#pragma unroll
    for (int p = 0; p < 4; p++)
        wr4[p] = *(const float4*)(wbase + (size_t)(p * 16) * OD + KCH);
    __syncthreads();

    for (int it = 0; it < NIT; ++it) {
        const uint32_t cur = (uint32_t)(it & 1) * STG;
        const uint32_t nxt = cur ^ STG;

        if (it + 1 < NIT) {
#pragma unroll
            for (int p = 0; p < 8; p++) {
                uint32_t off = (uint32_t)(rA + p * 16) * ROWP + cA * 8;
                store_x_h(sm, nxt + A_H + off, xr[p]);
            }
#pragma unroll
            for (int p = 0; p < 4; p++) {
                uint32_t off = (uint32_t)(rA + p * 16) * ROWP + cA * 8;
                split_store_w(sm, nxt + B_HI + off, nxt + B_LO + off, wr4[p]);
            }
        }
        if (it + 2 < NIT) {
            const int k2 = (it + 2) * KCH;
#pragma unroll
            for (int p = 0; p < 8; p++)
                xr[p] = *(const float4*)(xbase + (size_t)(p * 16) * OD + k2);
#pragma unroll
            for (int p = 0; p < 4; p++)
                wr4[p] = *(const float4*)(wbase + (size_t)(p * 16) * OD + k2);
        }

#pragma unroll
        for (int ks = 0; ks < 4; ks++) {
            uint32_t ah[2][4];
#pragma unroll
            for (int mt = 0; mt < 2; mt++) {
                uint32_t ao = cur + a_row_off + (uint32_t)mt * 16 * ROWP
                            + ks * 32;
                ldm4(ah[mt], sb + A_H + ao);
            }
#pragma unroll
            for (int nb = 0; nb < 2; nb++) {
                uint32_t bo = cur + b_row_off
                            + (uint32_t)(wc * 32 + nb * 16) * ROWP + ks * 32;
                uint32_t bh[4], bl[4];
                ldm4(bh, sb + B_HI + bo);
                ldm4(bl, sb + B_LO + bo);
#pragma unroll
                for (int mt = 0; mt < 2; mt++) {
#pragma unroll
                    for (int h = 0; h < 2; h++) {
                        float* c = acc[mt][nb * 2 + h];
                        mma_f16(c, ah[mt], bh + h * 2);
                        mma_f16(c, ah[mt], bl + h * 2);
                    }
                }
            }
        }
        __syncthreads();
    }

    if (mat != 2) {
        __half* Y = (mat == 0) ? g_Qh : g_Kh;
#pragma unroll
        for (int nt = 0; nt < 4; nt++) {
            int n0 = wc * 32 + nt * 8 + (lane & 3) * 2;
            float b0 = bias[n0], b1 = bias[n0 + 1];
#pragma unroll
            for (int mt = 0; mt < 2; mt++) {
#pragma unroll
                for (int ro = 0; ro < 2; ro++) {
                    int grow = row0 + wr * 32 + mt * 16 + (lane >> 2) + ro * 8;
                    int b = grow >> 9, l = grow & 511;
                    int x = b >> 4, mm = l & 15, pp = ((b & 15) << 5) | (l >> 4);
                    int hh = (x << 4) | mm;
                    uint32_t hbits = h2bits(acc[mt][nt][ro * 2 + 0] * WINV + b0,
                                            acc[mt][nt][ro * 2 + 1] * WINV + b1);
                    *(uint32_t*)(Y + ((size_t)hh * LL + pp) * DD + n0) = hbits;
                }
            }
        }
    } else {
        float* smf = (float*)sm;
#pragma unroll
        for (int nt = 0; nt < 4; nt++) {
            int n0 = wc * 32 + nt * 8 + (lane & 3) * 2;
            float b0 = bias[n0], b1 = bias[n0 + 1];
#pragma unroll
            for (int mt = 0; mt < 2; mt++) {
#pragma unroll
                for (int ro = 0; ro < 2; ro++) {
                    int r = wr * 32 + mt * 16 + (lane >> 2) + ro * 8;
                    smf[r * 65 + n0]     = acc[mt][nt][ro * 2 + 0] * WINV + b0;
                    smf[r * 65 + n0 + 1] = acc[mt][nt][ro * 2 + 1] * WINV + b1;
                }
            }
        }
        __syncthreads();

        const int bb  = row0 >> 9;
        const int xb  = bb >> 4;
        const int ppb = ((bb & 15) << 5) + ((row0 & 511) >> 4);
#pragma unroll
        for (int s = 0; s < 4; s++) {
            int idx = t + 256 * s;
            int hl  = idx & 15;
            int d   = idx >> 4;
            int hh  = (xb << 4) | hl;
            float v0 = smf[(hl + 16 * 0) * 65 + d];
            float v1 = smf[(hl + 16 * 1) * 65 + d];
            float v2 = smf[(hl + 16 * 2) * 65 + d];
            float v3 = smf[(hl + 16 * 3) * 65 + d];
            float v4 = smf[(hl + 16 * 4) * 65 + d];
            float v5 = smf[(hl + 16 * 5) * 65 + d];
            float v6 = smf[(hl + 16 * 6) * 65 + d];
            float v7 = smf[(hl + 16 * 7) * 65 + d];
            uint4 hv;
            hv.x = h2bits(v0, v1);
            hv.y = h2bits(v2, v3);
            hv.z = h2bits(v4, v5);
            hv.w = h2bits(v6, v7);
            *(uint4*)(g_Vh + ((size_t)hh * DD + d) * LL + ppb) = hv;
        }
    }
}

// ---------------------------------------------------------------------------
// Tensor-core flash attention — single-fp16 Q/K/V planes: 1 MMA per S-tile,
// 1 MMA per PV-tile; staging = pure uint4 copy. smem 27.6 KB.
// ---------------------------------------------------------------------------
#define AQ 0
#define AK 9216
#define AV 18432
#define ATTN_SMEM 27648

__global__ __launch_bounds__(128) void attn_tc(
    const int* __restrict__ Q_len, const int* __restrict__ V_len,
    float* __restrict__ out)
{
    const int hh = blockIdx.x;
    const int q0 = (7 - blockIdx.y) << 6;   // heavy tiles first
    const int x  = hh >> 4;
    const int mm = hh & 15;
    const int qlen = Q_len[x];
    const int vlen = V_len[x];
    const int t    = threadIdx.x;
    const int wid  = t >> 5;
    const int lane = t & 31;

    float* outb = out + (size_t)x * LL * OD + (size_t)mm * DD;

    if (q0 >= qlen) {
#pragma unroll
        for (int s = 0; s < 8; s++) {
            int v  = t + 128 * s;
            int r  = v >> 4;
            int dd = (v & 15) << 2;
            *(float4*)(outb + (size_t)(q0 + r) * OD + dd) =
                make_float4(0.f, 0.f, 0.f, 0.f);
        }
        return;
    }

    extern __shared__ char sm[];
    const uint32_t sb = smem_u32(sm);

    // stage Q (pure copy: 64 rows x 64 fp16)
    const __half* Qg = g_Qh + ((size_t)hh * LL + q0) * DD;
#pragma unroll
    for (int s = 0; s < 4; s++) {
        int v  = t + 128 * s;        // 0..511
        int r  = v >> 3;             // 0..63
        int dd = (v & 7) << 3;       // 0,8,...,56
        *(uint4*)(sm + AQ + (uint32_t)r * ROWP + dd * 2) =
            *(const uint4*)(Qg + r * DD + dd);
    }

    const uint32_t aoff = (uint32_t)(wid * 16 + (lane & 15)) * ROWP
                        + ((lane >> 4) & 1) * 16;
    const uint32_t boff = (uint32_t)((lane & 7) + ((lane & 16) >> 1)) * ROWP
                        + ((lane & 8) << 1);

    const int rq0 = q0 + wid * 16 + (lane >> 2);
    const int rq1 = rq0 + 8;

    float o_[8][4];
#pragma unroll
    for (int nt = 0; nt < 8; nt++)
#pragma unroll
        for (int j = 0; j < 4; j++) o_[nt][j] = 0.f;
    float m0 = -1e30f, m1 = -1e30f, l0 = 0.f, l1 = 0.f;

    const int kmaxi = min(q0 + 63, vlen - 1);
    const int nkt   = kmaxi >> 6;

    for (int kt = 0; kt <= nkt; kt++) {
        const int k0 = kt << 6;
        __syncthreads();
        const __half* Kg = g_Kh + ((size_t)hh * LL + k0) * DD;
        const __half* Vg = g_Vh + (size_t)hh * DD * LL + k0;
#pragma unroll
        for (int s = 0; s < 4; s++) {
            int v  = t + 128 * s;
            int r  = v >> 3;
            int dd = (v & 7) << 3;
            uint32_t off = (uint32_t)r * ROWP + dd * 2;
            *(uint4*)(sm + AK + off) = *(const uint4*)(Kg + r * DD + dd);
            *(uint4*)(sm + AV + off) = *(const uint4*)(Vg + (size_t)r * LL + dd);
        }
        __syncthreads();

        // ---- S = Q K^T (single fp16: 1 MMA per tile) ----
        float s_[8][4];
#pragma unroll
        for (int nt = 0; nt < 8; nt++)
#pragma unroll
            for (int j = 0; j < 4; j++) s_[nt][j] = 0.f;

#pragma unroll
        for (int ks = 0; ks < 4; ks++) {
            uint32_t qh[4];
            ldm4(qh, sb + AQ + aoff + ks * 32);
#pragma unroll
            for (int nb = 0; nb < 4; nb++) {
                uint32_t kh[4];
                ldm4(kh, sb + AK + boff + (uint32_t)nb * 16 * ROWP + ks * 32);
#pragma unroll
                for (int h = 0; h < 2; h++)
                    mma_f16(s_[nb * 2 + h], qh, kh + h * 2);
            }
        }

        // ---- mask + scale ----
#pragma unroll
        for (int nt = 0; nt < 8; nt++) {
#pragma unroll
            for (int c = 0; c < 2; c++) {
                int k = k0 + nt * 8 + (lane & 3) * 2 + c;
                bool kv_ok = (k < vlen);
                s_[nt][c]     = (kv_ok && k <= rq0) ? s_[nt][c] * QKSCALE
                                                    : -1e30f;
                s_[nt][2 + c] = (kv_ok && k <= rq1) ? s_[nt][2 + c] * QKSCALE
                                                    : -1e30f;
            }
        }

        // ---- online softmax ----
        float tm0 = -1e30f, tm1 = -1e30f;
#pragma unroll
        for (int nt = 0; nt < 8; nt++) {
            tm0 = fmaxf(tm0, fmaxf(s_[nt][0], s_[nt][1]));
            tm1 = fmaxf(tm1, fmaxf(s_[nt][2], s_[nt][3]));
        }
        tm0 = fmaxf(tm0, __shfl_xor_sync(0xffffffffu, tm0, 1));
        tm0 = fmaxf(tm0, __shfl_xor_sync(0xffffffffu, tm0, 2));
        tm1 = fmaxf(tm1, __shfl_xor_sync(0xffffffffu, tm1, 1));
        tm1 = fmaxf(tm1, __shfl_xor_sync(0xffffffffu, tm1, 2));

        float mn0 = fmaxf(m0, tm0), mn1 = fmaxf(m1, tm1);
        float a0 = __expf(m0 - mn0), a1 = __expf(m1 - mn1);
        float sum0 = 0.f, sum1 = 0.f;
#pragma unroll
        for (int nt = 0; nt < 8; nt++) {
            float p0 = __expf(s_[nt][0] - mn0);
            float p1 = __expf(s_[nt][1] - mn0);
            float p2 = __expf(s_[nt][2] - mn1);
            float p3 = __expf(s_[nt][3] - mn1);
            s_[nt][0] = p0; s_[nt][1] = p1; s_[nt][2] = p2; s_[nt][3] = p3;
            sum0 += p0 + p1;
            sum1 += p2 + p3;
        }
        sum0 += __shfl_xor_sync(0xffffffffu, sum0, 1);
        sum0 += __shfl_xor_sync(0xffffffffu, sum0, 2);
        sum1 += __shfl_xor_sync(0xffffffffu, sum1, 1);
        sum1 += __shfl_xor_sync(0xffffffffu, sum1, 2);
        m0 = mn0; m1 = mn1;
        l0 = l0 * a0 + sum0;
        l1 = l1 * a1 + sum1;
#pragma unroll
        for (int nt = 0; nt < 8; nt++) {
            o_[nt][0] *= a0; o_[nt][1] *= a0;
            o_[nt][2] *= a1; o_[nt][3] *= a1;
        }

        // ---- O += P V  (P fp16, V single fp16: 1 MMA per tile) ----
#pragma unroll
        for (int j = 0; j < 4; j++) {
            uint32_t ph[4];
            ph[0] = h2bits(s_[2 * j][0],     s_[2 * j][1]);
            ph[1] = h2bits(s_[2 * j][2],     s_[2 * j][3]);
            ph[2] = h2bits(s_[2 * j + 1][0], s_[2 * j + 1][1]);
            ph[3] = h2bits(s_[2 * j + 1][2], s_[2 * j + 1][3]);
#pragma unroll
            for (int nb = 0; nb < 4; nb++) {
                uint32_t vh[4];
                ldm4(vh, sb + AV + boff + (uint32_t)nb * 16 * ROWP + j * 32);
#pragma unroll
                for (int h = 0; h < 2; h++)
                    mma_f16(o_[nb * 2 + h], ph, vh + h * 2);
            }
        }
    }

    // ---- epilogue ----
    float inv0 = 1.f / l0, inv1 = 1.f / l1;
    bool ok0 = (rq0 < qlen), ok1 = (rq1 < qlen);
#pragma unroll
    for (int nt = 0; nt < 8; nt++) {
        int d = nt * 8 + (lane & 3) * 2;
        float2 w0, w1;
        w0.x = ok0 ? o_[nt][0] * inv0 : 0.f;
        w0.y = ok0 ? o_[nt][1] * inv0 : 0.f;
        w1.x = ok1 ? o_[nt][2] * inv1 : 0.f;
        w1.y = ok1 ? o_[nt][3] * inv1 : 0.f;
        *(float2*)(outb + (size_t)rq0 * OD + d) = w0;
        *(float2*)(outb + (size_t)rq1 * OD + d) = w1;
    }
}

// ---------------------------------------------------------------------------
extern "C" void kernel_launch(void* const* d_in, const int* in_sizes, int n_in,
                              void* d_out, int out_size)
{
    (void)in_sizes; (void)n_in; (void)out_size;
    const float* Qseq = (const float*)d_in[0];
    const float* Kseq = (const float*)d_in[1];
    const float* Vseq = (const float*)d_in[2];
    const int*   Qlen = (const int*)d_in[3];
    const int*   Vlen = (const int*)d_in[4];
    const float* WQw  = (const float*)d_in[5];
    const float* WQb  = (const float*)d_in[6];
    const float* WKw  = (const float*)d_in[7];
    const float* WKb  = (const float*)d_in[8];
    const float* WVw  = (const float*)d_in[9];
    const float* WVb  = (const float*)d_in[10];
    float* out = (float*)d_out;

    cudaFuncSetAttribute(proj_tc,
                         cudaFuncAttributeMaxDynamicSharedMemorySize, PROJ_SMEM);
    cudaFuncSetAttribute(attn_tc,
                         cudaFuncAttributeMaxDynamicSharedMemorySize, ATTN_SMEM);

    dim3 pg(256, 3);
    proj_tc<<<pg, 256, PROJ_SMEM>>>(Qseq, Kseq, Vseq,
                                    WQw, WKw, WVw,
                                    WQb, WKb, WVb);

    dim3 grid(64, 8);
    attn_tc<<<grid, 128, ATTN_SMEM>>>(Qlen, Vlen, out);
}